// round 1
// baseline (speedup 1.0000x reference)
#include <cuda_runtime.h>

// Problem constants (fixed by the dataset; runtime sizes read from in_sizes and
// guarded against these maxima).
#define NMAX 100000
#define EMAX 1600000

// ---------------- scratch (device globals: no runtime allocation) ------------
__device__ int   g_cnt[NMAX];      // real in-degree (excl. self loop)
__device__ int   g_fill[NMAX];     // CSR fill cursor
__device__ int   g_rowptr[NMAX];   // exclusive prefix sum of g_cnt
__device__ float g_dinv[NMAX];     // deg^{-1/2} (deg includes self loop)
__device__ int2  g_csr[EMAX];      // (src, __float_as_int(norm)) grouped by dst
__device__ float g_h1[(size_t)NMAX * 64];   // x @ W1
__device__ float g_a1[(size_t)NMAX * 64];   // relu(agg1 + b1)
__device__ float g_h2[(size_t)NMAX * 32];   // a1 @ W2
__device__ int   g_bsums[256];              // scan block sums

// ---------------- graph build ------------------------------------------------
__global__ void k_init(int n) {
    int i = blockIdx.x * blockDim.x + threadIdx.x;
    if (i < n) { g_cnt[i] = 0; g_fill[i] = 0; }
}

__global__ void k_degree(const int* __restrict__ dst, int e) {
    int i = blockIdx.x * blockDim.x + threadIdx.x;
    if (i < e) atomicAdd(&g_cnt[dst[i]], 1);
}

__global__ void k_dinv(int n) {
    int i = blockIdx.x * blockDim.x + threadIdx.x;
    if (i < n) g_dinv[i] = rsqrtf((float)(g_cnt[i] + 1));  // +1 = self loop
}

// 3-kernel exclusive scan of g_cnt -> g_rowptr (N up to 100352 = 98 blocks)
__global__ void k_scan_block_sums(int n) {
    __shared__ int s[1024];
    int i = blockIdx.x * 1024 + threadIdx.x;
    s[threadIdx.x] = (i < n) ? g_cnt[i] : 0;
    __syncthreads();
    for (int off = 512; off > 0; off >>= 1) {
        if (threadIdx.x < off) s[threadIdx.x] += s[threadIdx.x + off];
        __syncthreads();
    }
    if (threadIdx.x == 0) g_bsums[blockIdx.x] = s[0];
}

__global__ void k_scan_sums(int nb) {
    __shared__ int s[256];
    int t = threadIdx.x;
    if (t < nb) s[t] = g_bsums[t];
    __syncthreads();
    if (t == 0) {
        int acc = 0;
        for (int b = 0; b < nb; b++) { int v = s[b]; s[b] = acc; acc += v; }
    }
    __syncthreads();
    if (t < nb) g_bsums[t] = s[t];
}

__global__ void k_scan_final(int n) {
    __shared__ int buf0[1024], buf1[1024];
    int t = threadIdx.x;
    int i = blockIdx.x * 1024 + t;
    buf0[t] = (i < n) ? g_cnt[i] : 0;
    __syncthreads();
    int* s = buf0; int* d = buf1;
    for (int off = 1; off < 1024; off <<= 1) {
        int v = s[t];
        if (t >= off) v += s[t - off];
        d[t] = v;
        __syncthreads();
        int* tmp = s; s = d; d = tmp;
    }
    // s holds inclusive scan
    int excl = g_bsums[blockIdx.x] + (t ? s[t - 1] : 0);
    if (i < n) g_rowptr[i] = excl;
}

__global__ void k_scatter(const int* __restrict__ src, const int* __restrict__ dst, int e) {
    int i = blockIdx.x * blockDim.x + threadIdx.x;
    if (i < e) {
        int s = src[i], d = dst[i];
        int pos = g_rowptr[d] + atomicAdd(&g_fill[d], 1);
        g_csr[pos] = make_int2(s, __float_as_int(g_dinv[s] * g_dinv[d]));
    }
}

// ---------------- layer 1 GEMM: h1 = x @ W1  (N x 256 @ 256 x 64) -----------
// One warp per node; W1 staged in SMEM in two 128-row phases (32KB).
__global__ __launch_bounds__(256) void k_gemm1(const float* __restrict__ x,
                                               const float* __restrict__ W1, int n) {
    __shared__ float ws[128 * 64];
    int lane = threadIdx.x & 31;
    int warp = threadIdx.x >> 5;
    int node = blockIdx.x * 8 + warp;

    float xr[8];
    if (node < n) {
        const float* xp = x + (size_t)node * 256;
#pragma unroll
        for (int t = 0; t < 8; t++) xr[t] = xp[t * 32 + lane];
    }
    float2 acc = make_float2(0.f, 0.f);
#pragma unroll
    for (int p = 0; p < 2; p++) {
        __syncthreads();
        for (int idx = threadIdx.x; idx < 128 * 64; idx += 256)
            ws[idx] = W1[p * 128 * 64 + idx];
        __syncthreads();
        if (node < n) {
            const float2* ws2 = (const float2*)ws;
#pragma unroll
            for (int t = 0; t < 4; t++) {
                float xv0 = xr[p * 4 + t];
#pragma unroll
                for (int u = 0; u < 32; u++) {
                    float xv = __shfl_sync(0xffffffffu, xv0, u);
                    float2 w = ws2[(t * 32 + u) * 32 + lane];
                    acc.x = fmaf(xv, w.x, acc.x);
                    acc.y = fmaf(xv, w.y, acc.y);
                }
            }
        }
    }
    if (node < n) ((float2*)(g_h1 + (size_t)node * 64))[lane] = acc;
}

// ---------------- layer 1 aggregation: a1 = relu(sum norm*h1[src] + b1) -----
__global__ __launch_bounds__(256) void k_agg1(const float* __restrict__ b1, int n) {
    int lane = threadIdx.x & 31;
    int node = (blockIdx.x * blockDim.x + threadIdx.x) >> 5;
    if (node >= n) return;
    float di = g_dinv[node];
    float wself = di * di;
    const float2* hr = (const float2*)(g_h1 + (size_t)node * 64);
    float2 h0 = hr[lane];
    float2 acc = make_float2(wself * h0.x, wself * h0.y);
    int start = g_rowptr[node];
    int cnt = g_cnt[node];
    for (int base = 0; base < cnt; base += 32) {
        int rem = cnt - base;
        int2 ev = make_int2(0, 0);
        if (lane < rem) ev = g_csr[start + base + lane];
        int m = rem < 32 ? rem : 32;
        for (int j = 0; j < m; j++) {
            int s   = __shfl_sync(0xffffffffu, ev.x, j);
            float w = __int_as_float(__shfl_sync(0xffffffffu, ev.y, j));
            const float2* hs = (const float2*)(g_h1 + (size_t)s * 64);
            float2 hv = hs[lane];
            acc.x = fmaf(w, hv.x, acc.x);
            acc.y = fmaf(w, hv.y, acc.y);
        }
    }
    float2 bb = ((const float2*)b1)[lane];
    acc.x = fmaxf(acc.x + bb.x, 0.f);
    acc.y = fmaxf(acc.y + bb.y, 0.f);
    ((float2*)(g_a1 + (size_t)node * 64))[lane] = acc;
}

// ---------------- layer 2 GEMM: h2 = a1 @ W2  (N x 64 @ 64 x 32) ------------
__global__ __launch_bounds__(256) void k_gemm2(const float* __restrict__ W2, int n) {
    __shared__ float ws[64 * 32];
    for (int idx = threadIdx.x; idx < 64 * 32; idx += 256) ws[idx] = W2[idx];
    __syncthreads();
    int lane = threadIdx.x & 31;
    int node = blockIdx.x * 8 + (threadIdx.x >> 5);
    if (node >= n) return;
    const float* ar = g_a1 + (size_t)node * 64;
    float x0 = ar[lane], x1 = ar[32 + lane];
    float acc = 0.f;
#pragma unroll
    for (int u = 0; u < 32; u++) {
        float xv = __shfl_sync(0xffffffffu, x0, u);
        acc = fmaf(xv, ws[u * 32 + lane], acc);
    }
#pragma unroll
    for (int u = 0; u < 32; u++) {
        float xv = __shfl_sync(0xffffffffu, x1, u);
        acc = fmaf(xv, ws[(32 + u) * 32 + lane], acc);
    }
    g_h2[(size_t)node * 32 + lane] = acc;
}

// ------- layer 2 aggregation fused with final linear: out = relu(.)@Wlin+blin
__global__ __launch_bounds__(256) void k_agg2(const float* __restrict__ b2,
                                              const float* __restrict__ Wlin,
                                              const float* __restrict__ blin,
                                              float* __restrict__ out, int n) {
    int lane = threadIdx.x & 31;
    int node = (blockIdx.x * blockDim.x + threadIdx.x) >> 5;
    if (node >= n) return;
    float di = g_dinv[node];
    float wself = di * di;
    float acc = wself * g_h2[(size_t)node * 32 + lane];
    int start = g_rowptr[node];
    int cnt = g_cnt[node];
    for (int base = 0; base < cnt; base += 32) {
        int rem = cnt - base;
        int2 ev = make_int2(0, 0);
        if (lane < rem) ev = g_csr[start + base + lane];
        int m = rem < 32 ? rem : 32;
        for (int j = 0; j < m; j++) {
            int s   = __shfl_sync(0xffffffffu, ev.x, j);
            float w = __int_as_float(__shfl_sync(0xffffffffu, ev.y, j));
            acc = fmaf(w, g_h2[(size_t)s * 32 + lane], acc);
        }
    }
    float v = fmaxf(acc + b2[lane], 0.f);
    float p = v * Wlin[lane];
#pragma unroll
    for (int off = 16; off > 0; off >>= 1) p += __shfl_xor_sync(0xffffffffu, p, off);
    if (lane == 0) out[node] = p + blin[0];
}

// ---------------- launch ------------------------------------------------------
extern "C" void kernel_launch(void* const* d_in, const int* in_sizes, int n_in,
                              void* d_out, int out_size) {
    const float* x    = (const float*)d_in[0];
    const int*   ei   = (const int*)  d_in[1];
    const float* W1   = (const float*)d_in[2];
    const float* b1   = (const float*)d_in[3];
    const float* W2   = (const float*)d_in[4];
    const float* b2   = (const float*)d_in[5];
    const float* Wlin = (const float*)d_in[6];
    const float* blin = (const float*)d_in[7];
    float* out = (float*)d_out;

    int n = in_sizes[0] / 256;   // nodes
    int e = in_sizes[1] / 2;     // directed edges
    if (n > NMAX) n = NMAX;
    if (e > EMAX) e = EMAX;
    const int* src = ei;
    const int* dst = ei + e;

    int nb = (n + 1023) / 1024;

    k_init          <<<(n + 255) / 256, 256>>>(n);
    k_degree        <<<(e + 255) / 256, 256>>>(dst, e);
    k_dinv          <<<(n + 255) / 256, 256>>>(n);
    k_scan_block_sums<<<nb, 1024>>>(n);
    k_scan_sums     <<<1, 256>>>(nb);
    k_scan_final    <<<nb, 1024>>>(n);
    k_scatter       <<<(e + 255) / 256, 256>>>(src, dst, e);

    k_gemm1         <<<(n + 7) / 8, 256>>>(x, W1, n);
    k_agg1          <<<(n + 7) / 8, 256>>>(b1, n);
    k_gemm2         <<<(n + 7) / 8, 256>>>(W2, n);
    k_agg2          <<<(n + 7) / 8, 256>>>(b2, Wlin, blin, out, n);
}

// round 2
// speedup vs baseline: 1.8127x; 1.8127x over previous
#include <cuda_runtime.h>

#define NMAX 100000
#define EMAX 1600000

// ---------------- scratch (device globals) -----------------------------------
__device__ int   g_cnt[NMAX];
__device__ int   g_fill[NMAX];
__device__ int   g_rowptr[NMAX];
__device__ float g_dinv[NMAX];
__device__ int2  g_csr[EMAX];               // (src, bits(norm)) grouped by dst
__device__ float g_h1[(size_t)NMAX * 64];
__device__ float g_a1[(size_t)NMAX * 64];
__device__ float g_h2[(size_t)NMAX * 32];
__device__ int   g_bsums[256];

// ---------------- graph build ------------------------------------------------
__global__ void k_init(int n) {
    int i = blockIdx.x * blockDim.x + threadIdx.x;
    if (i < n) { g_cnt[i] = 0; g_fill[i] = 0; }
}

__global__ void k_degree(const int* __restrict__ dst, int e) {
    int i = blockIdx.x * blockDim.x + threadIdx.x;
    if (i < e) atomicAdd(&g_cnt[dst[i]], 1);
}

__global__ void k_dinv(int n) {
    int i = blockIdx.x * blockDim.x + threadIdx.x;
    if (i < n) g_dinv[i] = rsqrtf((float)(g_cnt[i] + 1));  // +1 self loop
}

__global__ void k_scan_block_sums(int n) {
    __shared__ int s[1024];
    int i = blockIdx.x * 1024 + threadIdx.x;
    s[threadIdx.x] = (i < n) ? g_cnt[i] : 0;
    __syncthreads();
    for (int off = 512; off > 0; off >>= 1) {
        if (threadIdx.x < off) s[threadIdx.x] += s[threadIdx.x + off];
        __syncthreads();
    }
    if (threadIdx.x == 0) g_bsums[blockIdx.x] = s[0];
}

__global__ void k_scan_sums(int nb) {
    __shared__ int s[256];
    int t = threadIdx.x;
    if (t < nb) s[t] = g_bsums[t];
    __syncthreads();
    if (t == 0) {
        int acc = 0;
        for (int b = 0; b < nb; b++) { int v = s[b]; s[b] = acc; acc += v; }
    }
    __syncthreads();
    if (t < nb) g_bsums[t] = s[t];
}

__global__ void k_scan_final(int n) {
    __shared__ int buf0[1024], buf1[1024];
    int t = threadIdx.x;
    int i = blockIdx.x * 1024 + t;
    buf0[t] = (i < n) ? g_cnt[i] : 0;
    __syncthreads();
    int* s = buf0; int* d = buf1;
    for (int off = 1; off < 1024; off <<= 1) {
        int v = s[t];
        if (t >= off) v += s[t - off];
        d[t] = v;
        __syncthreads();
        int* tmp = s; s = d; d = tmp;
    }
    int excl = g_bsums[blockIdx.x] + (t ? s[t - 1] : 0);
    if (i < n) g_rowptr[i] = excl;
}

__global__ void k_scatter(const int* __restrict__ src, const int* __restrict__ dst, int e) {
    int i = blockIdx.x * blockDim.x + threadIdx.x;
    if (i < e) {
        int s = src[i], d = dst[i];
        int pos = g_rowptr[d] + atomicAdd(&g_fill[d], 1);
        g_csr[pos] = make_int2(s, __float_as_int(g_dinv[s] * g_dinv[d]));
    }
}

// ---------------- tf32 mma helpers -------------------------------------------
__device__ __forceinline__ unsigned f2tf(float f) {
    unsigned r; asm("cvt.rna.tf32.f32 %0, %1;" : "=r"(r) : "f"(f)); return r;
}
__device__ __forceinline__ void mma_tf32(float* d, const unsigned* a, unsigned b0, unsigned b1) {
    asm volatile(
        "mma.sync.aligned.m16n8k8.row.col.f32.tf32.tf32.f32 "
        "{%0,%1,%2,%3}, {%4,%5,%6,%7}, {%8,%9}, {%0,%1,%2,%3};"
        : "+f"(d[0]), "+f"(d[1]), "+f"(d[2]), "+f"(d[3])
        : "r"(a[0]), "r"(a[1]), "r"(a[2]), "r"(a[3]), "r"(b0), "r"(b1));
}

// ------- layer 1 GEMM: h1 = x @ W1  (N x 256 @ 256 x 64), 3xTF32 tensor core
// Block = 256 threads (8 warps), 128 nodes/block (16 per warp).
// K chunked by 32; X chunk + split W chunk staged in smem with pad strides
// chosen conflict-free for the mma fragment access patterns.
#define XS_LD 36   // 32 + 4 pad:  bank = (4*grp + 8*k8 + qid) % 32 -> unique
#define WS_LD 68   // 64 + 4 pad:  bank = (4*qid + grp) % 32       -> unique
__global__ __launch_bounds__(256) void k_gemm1(const float* __restrict__ x,
                                               const float* __restrict__ W1, int n) {
    __shared__ float xs[128 * XS_LD];
    __shared__ float whi[32 * WS_LD];
    __shared__ float wlo[32 * WS_LD];
    int tid = threadIdx.x, lane = tid & 31, warp = tid >> 5;
    int node0 = blockIdx.x * 128;
    int grp = lane >> 2, qid = lane & 3;

    float d[8][4];
#pragma unroll
    for (int t = 0; t < 8; t++) { d[t][0] = d[t][1] = d[t][2] = d[t][3] = 0.f; }

    for (int kc = 0; kc < 8; kc++) {
        __syncthreads();
        // X chunk [128 x 32] via float4 (4 per thread)
#pragma unroll
        for (int i = 0; i < 4; i++) {
            int idx = tid + i * 256;        // 0..1023
            int row = idx >> 3;
            int c4  = idx & 7;
            float4 v = make_float4(0.f, 0.f, 0.f, 0.f);
            if (node0 + row < n)
                v = *(const float4*)(x + (size_t)(node0 + row) * 256 + kc * 32 + c4 * 4);
            float* p = xs + row * XS_LD + c4 * 4;
            p[0] = v.x; p[1] = v.y; p[2] = v.z; p[3] = v.w;
        }
        // W chunk [32 x 64] load + hi/lo split (8 per thread)
#pragma unroll
        for (int i = 0; i < 8; i++) {
            int idx = tid + i * 256;        // 0..2047
            int row = idx >> 6;
            int col = idx & 63;
            float f = W1[(kc * 32 + row) * 64 + col];
            unsigned hb = f2tf(f);
            float hf = __uint_as_float(hb);
            whi[row * WS_LD + col] = hf;
            wlo[row * WS_LD + col] = f - hf;
        }
        __syncthreads();

#pragma unroll
        for (int k8 = 0; k8 < 4; k8++) {
            int arow = warp * 16 + grp;
            int acol = k8 * 8 + qid;
            float a0 = xs[arow * XS_LD + acol];
            float a1 = xs[(arow + 8) * XS_LD + acol];
            float a2 = xs[arow * XS_LD + acol + 4];
            float a3 = xs[(arow + 8) * XS_LD + acol + 4];
            unsigned ah[4], al[4];
            ah[0] = f2tf(a0); al[0] = f2tf(a0 - __uint_as_float(ah[0]));
            ah[1] = f2tf(a1); al[1] = f2tf(a1 - __uint_as_float(ah[1]));
            ah[2] = f2tf(a2); al[2] = f2tf(a2 - __uint_as_float(ah[2]));
            ah[3] = f2tf(a3); al[3] = f2tf(a3 - __uint_as_float(ah[3]));
#pragma unroll
            for (int t = 0; t < 8; t++) {
                int brow = k8 * 8 + qid;
                int bcol = t * 8 + grp;
                unsigned bh0 = f2tf(whi[brow * WS_LD + bcol]);
                unsigned bh1 = f2tf(whi[(brow + 4) * WS_LD + bcol]);
                unsigned bl0 = f2tf(wlo[brow * WS_LD + bcol]);
                unsigned bl1 = f2tf(wlo[(brow + 4) * WS_LD + bcol]);
                mma_tf32(d[t], ah, bh0, bh1);   // Ah*Bh
                mma_tf32(d[t], al, bh0, bh1);   // Al*Bh
                mma_tf32(d[t], ah, bl0, bl1);   // Ah*Bl
            }
        }
    }

    // epilogue: c0,c1 -> (row, 2q..2q+1), c2,c3 -> (row+8, ...)
    int r0 = node0 + warp * 16 + grp;
    int r1 = r0 + 8;
#pragma unroll
    for (int t = 0; t < 8; t++) {
        int col = t * 8 + qid * 2;
        if (r0 < n) *(float2*)(g_h1 + (size_t)r0 * 64 + col) = make_float2(d[t][0], d[t][1]);
        if (r1 < n) *(float2*)(g_h1 + (size_t)r1 * 64 + col) = make_float2(d[t][2], d[t][3]);
    }
}

// ---------------- layer 1 aggregation (MLP=4 unroll) --------------------------
__global__ __launch_bounds__(256) void k_agg1(const float* __restrict__ b1, int n) {
    int lane = threadIdx.x & 31;
    int node = (blockIdx.x * blockDim.x + threadIdx.x) >> 5;
    if (node >= n) return;
    float di = g_dinv[node];
    float wself = di * di;
    float2 h0 = ((const float2*)(g_h1 + (size_t)node * 64))[lane];
    float2 acc  = make_float2(wself * h0.x, wself * h0.y);
    float2 acc2 = make_float2(0.f, 0.f);
    int start = g_rowptr[node];
    int cnt = g_cnt[node];
    for (int base = 0; base < cnt; base += 32) {
        int rem = cnt - base; if (rem > 32) rem = 32;
        int2 ev = make_int2(0, 0);
        if (lane < rem) ev = g_csr[start + base + lane];
        int j = 0;
        for (; j + 4 <= rem; j += 4) {
            int s0 = __shfl_sync(0xffffffffu, ev.x, j);
            int s1 = __shfl_sync(0xffffffffu, ev.x, j + 1);
            int s2 = __shfl_sync(0xffffffffu, ev.x, j + 2);
            int s3 = __shfl_sync(0xffffffffu, ev.x, j + 3);
            float w0 = __int_as_float(__shfl_sync(0xffffffffu, ev.y, j));
            float w1 = __int_as_float(__shfl_sync(0xffffffffu, ev.y, j + 1));
            float w2 = __int_as_float(__shfl_sync(0xffffffffu, ev.y, j + 2));
            float w3 = __int_as_float(__shfl_sync(0xffffffffu, ev.y, j + 3));
            float2 v0 = ((const float2*)(g_h1 + (size_t)s0 * 64))[lane];
            float2 v1 = ((const float2*)(g_h1 + (size_t)s1 * 64))[lane];
            float2 v2 = ((const float2*)(g_h1 + (size_t)s2 * 64))[lane];
            float2 v3 = ((const float2*)(g_h1 + (size_t)s3 * 64))[lane];
            acc.x  = fmaf(w0, v0.x, acc.x);  acc.y  = fmaf(w0, v0.y, acc.y);
            acc2.x = fmaf(w1, v1.x, acc2.x); acc2.y = fmaf(w1, v1.y, acc2.y);
            acc.x  = fmaf(w2, v2.x, acc.x);  acc.y  = fmaf(w2, v2.y, acc.y);
            acc2.x = fmaf(w3, v3.x, acc2.x); acc2.y = fmaf(w3, v3.y, acc2.y);
        }
        for (; j < rem; j++) {
            int s   = __shfl_sync(0xffffffffu, ev.x, j);
            float w = __int_as_float(__shfl_sync(0xffffffffu, ev.y, j));
            float2 hv = ((const float2*)(g_h1 + (size_t)s * 64))[lane];
            acc.x = fmaf(w, hv.x, acc.x);
            acc.y = fmaf(w, hv.y, acc.y);
        }
    }
    acc.x += acc2.x; acc.y += acc2.y;
    float2 bb = ((const float2*)b1)[lane];
    acc.x = fmaxf(acc.x + bb.x, 0.f);
    acc.y = fmaxf(acc.y + bb.y, 0.f);
    ((float2*)(g_a1 + (size_t)node * 64))[lane] = acc;
}

// ---------------- layer 2 GEMM: h2 = a1 @ W2 (N x 64 @ 64 x 32) --------------
__global__ __launch_bounds__(256) void k_gemm2(const float* __restrict__ W2, int n) {
    __shared__ float ws[64 * 32];
    for (int idx = threadIdx.x; idx < 64 * 32; idx += 256) ws[idx] = W2[idx];
    __syncthreads();
    int lane = threadIdx.x & 31;
    int node = blockIdx.x * 8 + (threadIdx.x >> 5);
    if (node >= n) return;
    const float* ar = g_a1 + (size_t)node * 64;
    float x0 = ar[lane], x1 = ar[32 + lane];
    float acc = 0.f;
#pragma unroll
    for (int u = 0; u < 32; u++) {
        float xv = __shfl_sync(0xffffffffu, x0, u);
        acc = fmaf(xv, ws[u * 32 + lane], acc);
    }
#pragma unroll
    for (int u = 0; u < 32; u++) {
        float xv = __shfl_sync(0xffffffffu, x1, u);
        acc = fmaf(xv, ws[(32 + u) * 32 + lane], acc);
    }
    g_h2[(size_t)node * 32 + lane] = acc;
}

// ------- layer 2 aggregation fused with final linear (MLP=4 unroll) ----------
__global__ __launch_bounds__(256) void k_agg2(const float* __restrict__ b2,
                                              const float* __restrict__ Wlin,
                                              const float* __restrict__ blin,
                                              float* __restrict__ out, int n) {
    int lane = threadIdx.x & 31;
    int node = (blockIdx.x * blockDim.x + threadIdx.x) >> 5;
    if (node >= n) return;
    float di = g_dinv[node];
    float wself = di * di;
    float acc  = wself * g_h2[(size_t)node * 32 + lane];
    float acc2 = 0.f;
    int start = g_rowptr[node];
    int cnt = g_cnt[node];
    for (int base = 0; base < cnt; base += 32) {
        int rem = cnt - base; if (rem > 32) rem = 32;
        int2 ev = make_int2(0, 0);
        if (lane < rem) ev = g_csr[start + base + lane];
        int j = 0;
        for (; j + 4 <= rem; j += 4) {
            int s0 = __shfl_sync(0xffffffffu, ev.x, j);
            int s1 = __shfl_sync(0xffffffffu, ev.x, j + 1);
            int s2 = __shfl_sync(0xffffffffu, ev.x, j + 2);
            int s3 = __shfl_sync(0xffffffffu, ev.x, j + 3);
            float w0 = __int_as_float(__shfl_sync(0xffffffffu, ev.y, j));
            float w1 = __int_as_float(__shfl_sync(0xffffffffu, ev.y, j + 1));
            float w2 = __int_as_float(__shfl_sync(0xffffffffu, ev.y, j + 2));
            float w3 = __int_as_float(__shfl_sync(0xffffffffu, ev.y, j + 3));
            float v0 = g_h2[(size_t)s0 * 32 + lane];
            float v1 = g_h2[(size_t)s1 * 32 + lane];
            float v2 = g_h2[(size_t)s2 * 32 + lane];
            float v3 = g_h2[(size_t)s3 * 32 + lane];
            acc  = fmaf(w0, v0, acc);
            acc2 = fmaf(w1, v1, acc2);
            acc  = fmaf(w2, v2, acc);
            acc2 = fmaf(w3, v3, acc2);
        }
        for (; j < rem; j++) {
            int s   = __shfl_sync(0xffffffffu, ev.x, j);
            float w = __int_as_float(__shfl_sync(0xffffffffu, ev.y, j));
            acc = fmaf(w, g_h2[(size_t)s * 32 + lane], acc);
        }
    }
    acc += acc2;
    float v = fmaxf(acc + b2[lane], 0.f);
    float p = v * Wlin[lane];
#pragma unroll
    for (int off = 16; off > 0; off >>= 1) p += __shfl_xor_sync(0xffffffffu, p, off);
    if (lane == 0) out[node] = p + blin[0];
}

// ---------------- launch -------------------------------------------------------
extern "C" void kernel_launch(void* const* d_in, const int* in_sizes, int n_in,
                              void* d_out, int out_size) {
    const float* x    = (const float*)d_in[0];
    const int*   ei   = (const int*)  d_in[1];
    const float* W1   = (const float*)d_in[2];
    const float* b1   = (const float*)d_in[3];
    const float* W2   = (const float*)d_in[4];
    const float* b2   = (const float*)d_in[5];
    const float* Wlin = (const float*)d_in[6];
    const float* blin = (const float*)d_in[7];
    float* out = (float*)d_out;

    int n = in_sizes[0] / 256;
    int e = in_sizes[1] / 2;
    if (n > NMAX) n = NMAX;
    if (e > EMAX) e = EMAX;
    const int* src = ei;
    const int* dst = ei + e;

    int nb = (n + 1023) / 1024;

    k_init           <<<(n + 255) / 256, 256>>>(n);
    k_degree         <<<(e + 255) / 256, 256>>>(dst, e);
    k_dinv           <<<(n + 255) / 256, 256>>>(n);
    k_scan_block_sums<<<nb, 1024>>>(n);
    k_scan_sums      <<<1, 256>>>(nb);
    k_scan_final     <<<nb, 1024>>>(n);
    k_scatter        <<<(e + 255) / 256, 256>>>(src, dst, e);

    k_gemm1          <<<(n + 127) / 128, 256>>>(x, W1, n);
    k_agg1           <<<(n + 7) / 8, 256>>>(b1, n);
    k_gemm2          <<<(n + 7) / 8, 256>>>(W2, n);
    k_agg2           <<<(n + 7) / 8, 256>>>(b2, Wlin, blin, out, n);
}

// round 3
// speedup vs baseline: 1.8734x; 1.0335x over previous
#include <cuda_runtime.h>

#define NMAX 100000
#define EMAX 1600000

// ---------------- scratch (device globals) -----------------------------------
__device__ int   g_cnt[NMAX];
__device__ int   g_fill[NMAX];
__device__ int   g_rowptr[NMAX];
__device__ float g_dinv[NMAX];
__device__ int2  g_csr[EMAX];               // (src, bits(norm)) grouped by dst
__device__ float g_h1[(size_t)NMAX * 64];
__device__ float g_h2[(size_t)NMAX * 32];
__device__ int   g_bsums[256];

// ---------------- graph build ------------------------------------------------
__global__ void k_init(int n) {
    int i = blockIdx.x * blockDim.x + threadIdx.x;
    if (i < n) { g_cnt[i] = 0; g_fill[i] = 0; }
}

__global__ void k_degree(const int* __restrict__ dst, int e) {
    int i = blockIdx.x * blockDim.x + threadIdx.x;
    if (i < e) atomicAdd(&g_cnt[dst[i]], 1);
}

__global__ void k_scan_block_sums(int n) {
    __shared__ int s[1024];
    int i = blockIdx.x * 1024 + threadIdx.x;
    s[threadIdx.x] = (i < n) ? g_cnt[i] : 0;
    __syncthreads();
    for (int off = 512; off > 0; off >>= 1) {
        if (threadIdx.x < off) s[threadIdx.x] += s[threadIdx.x + off];
        __syncthreads();
    }
    if (threadIdx.x == 0) g_bsums[blockIdx.x] = s[0];
}

__global__ void k_scan_sums(int nb) {
    __shared__ int s[256];
    int t = threadIdx.x;
    if (t < nb) s[t] = g_bsums[t];
    __syncthreads();
    if (t == 0) {
        int acc = 0;
        for (int b = 0; b < nb; b++) { int v = s[b]; s[b] = acc; acc += v; }
    }
    __syncthreads();
    if (t < nb) g_bsums[t] = s[t];
}

// exclusive scan of cnt -> rowptr, plus dinv = rsqrt(cnt+1) (folded in)
__global__ void k_scan_final(int n) {
    __shared__ int buf0[1024], buf1[1024];
    int t = threadIdx.x;
    int i = blockIdx.x * 1024 + t;
    int c = (i < n) ? g_cnt[i] : 0;
    buf0[t] = c;
    __syncthreads();
    int* s = buf0; int* d = buf1;
    for (int off = 1; off < 1024; off <<= 1) {
        int v = s[t];
        if (t >= off) v += s[t - off];
        d[t] = v;
        __syncthreads();
        int* tmp = s; s = d; d = tmp;
    }
    int excl = g_bsums[blockIdx.x] + (t ? s[t - 1] : 0);
    if (i < n) {
        g_rowptr[i] = excl;
        g_dinv[i] = rsqrtf((float)(c + 1));   // +1 self loop
    }
}

__global__ void k_scatter(const int* __restrict__ src, const int* __restrict__ dst, int e) {
    int i = blockIdx.x * blockDim.x + threadIdx.x;
    if (i < e) {
        int s = src[i], d = dst[i];
        int pos = g_rowptr[d] + atomicAdd(&g_fill[d], 1);
        g_csr[pos] = make_int2(s, __float_as_int(g_dinv[s] * g_dinv[d]));
    }
}

// ---------------- tf32 mma helpers -------------------------------------------
__device__ __forceinline__ unsigned f2tf(float f) {
    unsigned r; asm("cvt.rna.tf32.f32 %0, %1;" : "=r"(r) : "f"(f)); return r;
}
__device__ __forceinline__ void mma_tf32(float* d, const unsigned* a, unsigned b0, unsigned b1) {
    asm volatile(
        "mma.sync.aligned.m16n8k8.row.col.f32.tf32.tf32.f32 "
        "{%0,%1,%2,%3}, {%4,%5,%6,%7}, {%8,%9}, {%0,%1,%2,%3};"
        : "+f"(d[0]), "+f"(d[1]), "+f"(d[2]), "+f"(d[3])
        : "r"(a[0]), "r"(a[1]), "r"(a[2]), "r"(a[3]), "r"(b0), "r"(b1));
}

// ------- layer 1 GEMM: h1 = x @ W1 (N x 256 @ 256 x 64), 3xTF32 --------------
#define XS_LD 36
#define WS_LD 68
__global__ __launch_bounds__(256) void k_gemm1(const float* __restrict__ x,
                                               const float* __restrict__ W1, int n) {
    __shared__ float xs[128 * XS_LD];
    __shared__ float whi[32 * WS_LD];
    __shared__ float wlo[32 * WS_LD];
    int tid = threadIdx.x, lane = tid & 31, warp = tid >> 5;
    int node0 = blockIdx.x * 128;
    int grp = lane >> 2, qid = lane & 3;

    float d[8][4];
#pragma unroll
    for (int t = 0; t < 8; t++) { d[t][0] = d[t][1] = d[t][2] = d[t][3] = 0.f; }

    for (int kc = 0; kc < 8; kc++) {
        __syncthreads();
#pragma unroll
        for (int i = 0; i < 4; i++) {
            int idx = tid + i * 256;
            int row = idx >> 3;
            int c4  = idx & 7;
            float4 v = make_float4(0.f, 0.f, 0.f, 0.f);
            if (node0 + row < n)
                v = *(const float4*)(x + (size_t)(node0 + row) * 256 + kc * 32 + c4 * 4);
            float* p = xs + row * XS_LD + c4 * 4;
            p[0] = v.x; p[1] = v.y; p[2] = v.z; p[3] = v.w;
        }
#pragma unroll
        for (int i = 0; i < 8; i++) {
            int idx = tid + i * 256;
            int row = idx >> 6;
            int col = idx & 63;
            float f = W1[(kc * 32 + row) * 64 + col];
            unsigned hb = f2tf(f);
            float hf = __uint_as_float(hb);
            whi[row * WS_LD + col] = hf;
            wlo[row * WS_LD + col] = f - hf;
        }
        __syncthreads();

#pragma unroll
        for (int k8 = 0; k8 < 4; k8++) {
            int arow = warp * 16 + grp;
            int acol = k8 * 8 + qid;
            float a0 = xs[arow * XS_LD + acol];
            float a1 = xs[(arow + 8) * XS_LD + acol];
            float a2 = xs[arow * XS_LD + acol + 4];
            float a3 = xs[(arow + 8) * XS_LD + acol + 4];
            unsigned ah[4], al[4];
            ah[0] = f2tf(a0); al[0] = f2tf(a0 - __uint_as_float(ah[0]));
            ah[1] = f2tf(a1); al[1] = f2tf(a1 - __uint_as_float(ah[1]));
            ah[2] = f2tf(a2); al[2] = f2tf(a2 - __uint_as_float(ah[2]));
            ah[3] = f2tf(a3); al[3] = f2tf(a3 - __uint_as_float(ah[3]));
#pragma unroll
            for (int t = 0; t < 8; t++) {
                int brow = k8 * 8 + qid;
                int bcol = t * 8 + grp;
                unsigned bh0 = f2tf(whi[brow * WS_LD + bcol]);
                unsigned bh1 = f2tf(whi[(brow + 4) * WS_LD + bcol]);
                unsigned bl0 = f2tf(wlo[brow * WS_LD + bcol]);
                unsigned bl1 = f2tf(wlo[(brow + 4) * WS_LD + bcol]);
                mma_tf32(d[t], ah, bh0, bh1);
                mma_tf32(d[t], al, bh0, bh1);
                mma_tf32(d[t], ah, bl0, bl1);
            }
        }
    }

    int r0 = node0 + warp * 16 + grp;
    int r1 = r0 + 8;
#pragma unroll
    for (int t = 0; t < 8; t++) {
        int col = t * 8 + qid * 2;
        if (r0 < n) *(float2*)(g_h1 + (size_t)r0 * 64 + col) = make_float2(d[t][0], d[t][1]);
        if (r1 < n) *(float2*)(g_h1 + (size_t)r1 * 64 + col) = make_float2(d[t][2], d[t][3]);
    }
}

// ---- layer 1 agg + relu + fused gemm2: h2 = relu(agg(h1)+b1) @ W2 -----------
// One warp per node. Edge loop: uniform int2 loads (broadcast) + 8-way MLP.
__global__ __launch_bounds__(256) void k_agg1_gemm2(const float* __restrict__ b1,
                                                    const float* __restrict__ W2, int n) {
    __shared__ float ws[64 * 32];
    for (int idx = threadIdx.x; idx < 64 * 32; idx += 256) ws[idx] = W2[idx];
    __syncthreads();

    int lane = threadIdx.x & 31;
    int node = (blockIdx.x * blockDim.x + threadIdx.x) >> 5;
    if (node >= n) return;

    float di = g_dinv[node];
    float wself = di * di;
    float2 h0 = ((const float2*)(g_h1 + (size_t)node * 64))[lane];
    float2 acc0 = make_float2(wself * h0.x, wself * h0.y);
    float2 acc1 = make_float2(0.f, 0.f);
    float2 acc2 = make_float2(0.f, 0.f);
    float2 acc3 = make_float2(0.f, 0.f);

    const int2* ep = g_csr + g_rowptr[node];
    int cnt = g_cnt[node];
    int k = 0;
    for (; k + 8 <= cnt; k += 8) {
        int2 e0 = ep[k];     int2 e1 = ep[k + 1];
        int2 e2 = ep[k + 2]; int2 e3 = ep[k + 3];
        int2 e4 = ep[k + 4]; int2 e5 = ep[k + 5];
        int2 e6 = ep[k + 6]; int2 e7 = ep[k + 7];
        float2 v0 = ((const float2*)(g_h1 + (size_t)e0.x * 64))[lane];
        float2 v1 = ((const float2*)(g_h1 + (size_t)e1.x * 64))[lane];
        float2 v2 = ((const float2*)(g_h1 + (size_t)e2.x * 64))[lane];
        float2 v3 = ((const float2*)(g_h1 + (size_t)e3.x * 64))[lane];
        float2 v4 = ((const float2*)(g_h1 + (size_t)e4.x * 64))[lane];
        float2 v5 = ((const float2*)(g_h1 + (size_t)e5.x * 64))[lane];
        float2 v6 = ((const float2*)(g_h1 + (size_t)e6.x * 64))[lane];
        float2 v7 = ((const float2*)(g_h1 + (size_t)e7.x * 64))[lane];
        float w0 = __int_as_float(e0.y), w1 = __int_as_float(e1.y);
        float w2 = __int_as_float(e2.y), w3 = __int_as_float(e3.y);
        float w4 = __int_as_float(e4.y), w5 = __int_as_float(e5.y);
        float w6 = __int_as_float(e6.y), w7 = __int_as_float(e7.y);
        acc0.x = fmaf(w0, v0.x, acc0.x); acc0.y = fmaf(w0, v0.y, acc0.y);
        acc1.x = fmaf(w1, v1.x, acc1.x); acc1.y = fmaf(w1, v1.y, acc1.y);
        acc2.x = fmaf(w2, v2.x, acc2.x); acc2.y = fmaf(w2, v2.y, acc2.y);
        acc3.x = fmaf(w3, v3.x, acc3.x); acc3.y = fmaf(w3, v3.y, acc3.y);
        acc0.x = fmaf(w4, v4.x, acc0.x); acc0.y = fmaf(w4, v4.y, acc0.y);
        acc1.x = fmaf(w5, v5.x, acc1.x); acc1.y = fmaf(w5, v5.y, acc1.y);
        acc2.x = fmaf(w6, v6.x, acc2.x); acc2.y = fmaf(w6, v6.y, acc2.y);
        acc3.x = fmaf(w7, v7.x, acc3.x); acc3.y = fmaf(w7, v7.y, acc3.y);
    }
    for (; k < cnt; k++) {
        int2 e = ep[k];
        float w = __int_as_float(e.y);
        float2 v = ((const float2*)(g_h1 + (size_t)e.x * 64))[lane];
        acc0.x = fmaf(w, v.x, acc0.x);
        acc0.y = fmaf(w, v.y, acc0.y);
    }
    acc0.x += acc1.x + acc2.x + acc3.x;
    acc0.y += acc1.y + acc2.y + acc3.y;

    // relu + bias -> a1 row held in registers (lane has features 2l, 2l+1)
    float2 bb = ((const float2*)b1)[lane];
    float ax = fmaxf(acc0.x + bb.x, 0.f);
    float ay = fmaxf(acc0.y + bb.y, 0.f);

    // fused gemv: h2[col=lane] = sum_f a1[f] * W2[f][col]
    float h = 0.f;
#pragma unroll
    for (int u = 0; u < 32; u++) {
        float f0 = __shfl_sync(0xffffffffu, ax, u);
        float f1 = __shfl_sync(0xffffffffu, ay, u);
        h = fmaf(f0, ws[(2 * u) * 32 + lane], h);
        h = fmaf(f1, ws[(2 * u + 1) * 32 + lane], h);
    }
    g_h2[(size_t)node * 32 + lane] = h;
}

// ------- layer 2 agg fused with final linear ---------------------------------
__global__ __launch_bounds__(256) void k_agg2(const float* __restrict__ b2,
                                              const float* __restrict__ Wlin,
                                              const float* __restrict__ blin,
                                              float* __restrict__ out, int n) {
    int lane = threadIdx.x & 31;
    int node = (blockIdx.x * blockDim.x + threadIdx.x) >> 5;
    if (node >= n) return;

    float di = g_dinv[node];
    float wself = di * di;
    float acc0 = wself * g_h2[(size_t)node * 32 + lane];
    float acc1 = 0.f, acc2 = 0.f, acc3 = 0.f;

    const int2* ep = g_csr + g_rowptr[node];
    int cnt = g_cnt[node];
    int k = 0;
    for (; k + 8 <= cnt; k += 8) {
        int2 e0 = ep[k];     int2 e1 = ep[k + 1];
        int2 e2 = ep[k + 2]; int2 e3 = ep[k + 3];
        int2 e4 = ep[k + 4]; int2 e5 = ep[k + 5];
        int2 e6 = ep[k + 6]; int2 e7 = ep[k + 7];
        float v0 = g_h2[(size_t)e0.x * 32 + lane];
        float v1 = g_h2[(size_t)e1.x * 32 + lane];
        float v2 = g_h2[(size_t)e2.x * 32 + lane];
        float v3 = g_h2[(size_t)e3.x * 32 + lane];
        float v4 = g_h2[(size_t)e4.x * 32 + lane];
        float v5 = g_h2[(size_t)e5.x * 32 + lane];
        float v6 = g_h2[(size_t)e6.x * 32 + lane];
        float v7 = g_h2[(size_t)e7.x * 32 + lane];
        acc0 = fmaf(__int_as_float(e0.y), v0, acc0);
        acc1 = fmaf(__int_as_float(e1.y), v1, acc1);
        acc2 = fmaf(__int_as_float(e2.y), v2, acc2);
        acc3 = fmaf(__int_as_float(e3.y), v3, acc3);
        acc0 = fmaf(__int_as_float(e4.y), v4, acc0);
        acc1 = fmaf(__int_as_float(e5.y), v5, acc1);
        acc2 = fmaf(__int_as_float(e6.y), v6, acc2);
        acc3 = fmaf(__int_as_float(e7.y), v7, acc3);
    }
    for (; k < cnt; k++) {
        int2 e = ep[k];
        acc0 = fmaf(__int_as_float(e.y), g_h2[(size_t)e.x * 32 + lane], acc0);
    }
    acc0 += acc1 + acc2 + acc3;

    float v = fmaxf(acc0 + b2[lane], 0.f);
    float p = v * Wlin[lane];
#pragma unroll
    for (int off = 16; off > 0; off >>= 1) p += __shfl_xor_sync(0xffffffffu, p, off);
    if (lane == 0) out[node] = p + blin[0];
}

// ---------------- launch -------------------------------------------------------
extern "C" void kernel_launch(void* const* d_in, const int* in_sizes, int n_in,
                              void* d_out, int out_size) {
    const float* x    = (const float*)d_in[0];
    const int*   ei   = (const int*)  d_in[1];
    const float* W1   = (const float*)d_in[2];
    const float* b1   = (const float*)d_in[3];
    const float* W2   = (const float*)d_in[4];
    const float* b2   = (const float*)d_in[5];
    const float* Wlin = (const float*)d_in[6];
    const float* blin = (const float*)d_in[7];
    float* out = (float*)d_out;

    int n = in_sizes[0] / 256;
    int e = in_sizes[1] / 2;
    if (n > NMAX) n = NMAX;
    if (e > EMAX) e = EMAX;
    const int* src = ei;
    const int* dst = ei + e;

    int nb = (n + 1023) / 1024;

    k_init           <<<(n + 255) / 256, 256>>>(n);
    k_degree         <<<(e + 255) / 256, 256>>>(dst, e);
    k_scan_block_sums<<<nb, 1024>>>(n);
    k_scan_sums      <<<1, 256>>>(nb);
    k_scan_final     <<<nb, 1024>>>(n);
    k_scatter        <<<(e + 255) / 256, 256>>>(src, dst, e);

    k_gemm1          <<<(n + 127) / 128, 256>>>(x, W1, n);
    k_agg1_gemm2     <<<(n + 7) / 8, 256>>>(b1, W2, n);
    k_agg2           <<<(n + 7) / 8, 256>>>(b2, Wlin, blin, out, n);
}